// round 13
// baseline (speedup 1.0000x reference)
#include <cuda_runtime.h>
#include <cuda_bf16.h>
#include <cstdint>

#define NZ 64
#define NC 16
#define ND 64
#define NP 65536
#define LN_EPS 1e-5f

typedef unsigned long long ull;

// Prepped constants
__device__ uint32_t g_wpk_hi[8 * ND];    // [kpair][d] hi bf16x2
__device__ uint32_t g_wpk_lo[8 * ND];    // residual bf16x2
// zpart in MMA-fragment order: [j][z][t] float4
__device__ float4 g_zpf[4 * NZ * 4];

__device__ __forceinline__ uint32_t pk_bf16(float hi, float lo) {
    uint32_t r;
    asm("cvt.rn.bf16x2.f32 %0, %1, %2;" : "=r"(r) : "f"(hi), "f"(lo));
    return r;
}

// float4 (c 4t..4t+3) -> two hi bf16x2 + two residual bf16x2
__device__ __forceinline__ void cvt4(float4 f, uint32_t& hxy, uint32_t& hzw,
                                     uint32_t& lxy, uint32_t& lzw) {
    hxy = pk_bf16(f.y, f.x);
    hzw = pk_bf16(f.w, f.z);
    float r0 = f.x - __uint_as_float(hxy << 16);
    float r1 = f.y - __uint_as_float(hxy & 0xFFFF0000u);
    float r2 = f.z - __uint_as_float(hzw << 16);
    float r3 = f.w - __uint_as_float(hzw & 0xFFFF0000u);
    lxy = pk_bf16(r1, r0);
    lzw = pk_bf16(r3, r2);
}

// D = A*B + C
__device__ __forceinline__ void mma_c(float& d0, float& d1, float& d2, float& d3,
                                      uint32_t a0, uint32_t a1, uint32_t a2, uint32_t a3,
                                      uint32_t b0, uint32_t b1,
                                      float c0, float c1, float c2, float c3) {
    asm("mma.sync.aligned.m16n8k16.row.col.f32.bf16.bf16.f32 "
        "{%0,%1,%2,%3},{%4,%5,%6,%7},{%8,%9},{%10,%11,%12,%13};"
        : "=f"(d0), "=f"(d1), "=f"(d2), "=f"(d3)
        : "r"(a0), "r"(a1), "r"(a2), "r"(a3), "r"(b0), "r"(b1),
          "f"(c0), "f"(c1), "f"(c2), "f"(c3));
}
// D += A*B
__device__ __forceinline__ void mma_a(float& d0, float& d1, float& d2, float& d3,
                                      uint32_t a0, uint32_t a1, uint32_t a2, uint32_t a3,
                                      uint32_t b0, uint32_t b1) {
    asm("mma.sync.aligned.m16n8k16.row.col.f32.bf16.bf16.f32 "
        "{%0,%1,%2,%3},{%4,%5,%6,%7},{%8,%9},{%0,%1,%2,%3};"
        : "+f"(d0), "+f"(d1), "+f"(d2), "+f"(d3)
        : "r"(a0), "r"(a1), "r"(a2), "r"(a3), "r"(b0), "r"(b1));
}

// relu 4 outputs, packed f32x2 accumulate
__device__ __forceinline__ void relu_acc2(ull& acc, float d0, float d1,
                                          float d2, float d3) {
    asm("{\n\t"
        ".reg .f32 r0, r1, r2, r3;\n\t"
        ".reg .b64 p, q;\n\t"
        "max.f32 r0, %1, 0f00000000;\n\t"
        "max.f32 r1, %2, 0f00000000;\n\t"
        "max.f32 r2, %3, 0f00000000;\n\t"
        "max.f32 r3, %4, 0f00000000;\n\t"
        "mov.b64 p, {r0, r1};\n\t"
        "mov.b64 q, {r2, r3};\n\t"
        "add.rn.f32x2 p, p, q;\n\t"
        "add.rn.f32x2 %0, %0, p;\n\t"
        "}"
        : "+l"(acc)
        : "f"(d0), "f"(d1), "f"(d2), "f"(d3));
}
__device__ __forceinline__ void unpk64(ull v, float& a, float& b) {
    asm("mov.b64 {%0, %1}, %2;" : "=f"(a), "=f"(b) : "l"(v));
}

// cp.async 16B global->shared
__device__ __forceinline__ void cp16(uint32_t smem_dst, const void* gsrc) {
    asm volatile("cp.async.cg.shared.global [%0], [%1], 16;\n"
                 :: "r"(smem_dst), "l"(gsrc) : "memory");
}
__device__ __forceinline__ void cp_commit() {
    asm volatile("cp.async.commit_group;\n" ::: "memory");
}
template <int N>
__device__ __forceinline__ void cp_wait() {
    asm volatile("cp.async.wait_group %0;\n" :: "n"(N) : "memory");
}

// ---------------------------------------------------------------------------
// Prologue — grid-wide
// ---------------------------------------------------------------------------
__global__ void prep_kernel(const float* __restrict__ z_embed,
                            const float* __restrict__ w1,
                            const float* __restrict__ b1) {
    int tt = blockIdx.x * blockDim.x + threadIdx.x;
    int stride = gridDim.x * blockDim.x;
    for (int i = tt; i < NZ * ND; i += stride) {
        int z = i >> 6, d = i & 63;
        float s = b1[d];
#pragma unroll
        for (int c = 0; c < NC; c++)
            s += z_embed[z * NC + c] * w1[(NC + c) * ND + d];
        int j = d >> 4, r = d & 15;
        int t = (r & 7) >> 1;
        int slot = ((r >> 3) << 1) | (r & 1);
        ((float*)g_zpf)[(((j * NZ) + z) * 4 + t) * 4 + slot] = s;
    }
    for (int i = tt; i < 8 * ND; i += stride) {
        int kp = i >> 6, d = i & 63;
        float w0 = w1[(2 * kp) * ND + d];
        float w1v = w1[(2 * kp + 1) * ND + d];
        uint32_t hi = pk_bf16(w1v, w0);
        float h0 = __uint_as_float(hi << 16);
        float h1 = __uint_as_float(hi & 0xFFFF0000u);
        g_wpk_hi[i] = hi;
        g_wpk_lo[i] = pk_bf16(w1v - h1, w0 - h0);
    }
}

// ---------------------------------------------------------------------------
// Main: 1 warp = 4 pillars; zq + B-frags amortized 4x; cp.async pipeline
// ---------------------------------------------------------------------------
__global__ __launch_bounds__(128, 3)
void bev_hmma(const float* __restrict__ vol,
              const float* __restrict__ gamma_,
              const float* __restrict__ beta_,
              float* __restrict__ out) {
    // per-warp double buffers: 4 pillars x 1KB chunk = 4KB per (warp, buf)
    __shared__ __align__(16) float s_x[4][2][1024];

    int tid = threadIdx.x;
    int warp = tid >> 5, lane = tid & 31;
    int g = lane >> 2, t = lane & 3;
    int quad = blockIdx.x * 4 + warp;          // 4 pillars per warp

    // B fragments under K-permutation: b0 <-> kp 2t, b1 <-> kp 2t+1
    uint32_t BH0[8], BH1[8], BL0[8], BL1[8];
#pragma unroll
    for (int nt = 0; nt < 8; nt++) {
        int n = nt * 8 + g;
        BH0[nt] = g_wpk_hi[(2 * t) * ND + n];
        BH1[nt] = g_wpk_hi[(2 * t + 1) * ND + n];
        BL0[nt] = g_wpk_lo[(2 * t) * ND + n];
        BL1[nt] = g_wpk_lo[(2 * t + 1) * ND + n];
    }

    const float* gbase = vol + (size_t)quad * 4096;   // pillar quad*4

    uint32_t sb[2];
    sb[0] = (uint32_t)__cvta_generic_to_shared(&s_x[warp][0][0]);
    sb[1] = (uint32_t)__cvta_generic_to_shared(&s_x[warp][1][0]);

    // stage one chunk for 4 pillars (4KB): 8 x cp16 per lane, coalesced
    auto issue = [&](int buf, int c) {
        uint32_t d0 = sb[buf] + lane * 16;
        const float* src = gbase + c * 256 + lane * 4;
#pragma unroll
        for (int p = 0; p < 4; p++) {
            cp16(d0 + p * 1024, src + p * 1024);
            cp16(d0 + p * 1024 + 512, src + p * 1024 + 128);
        }
        cp_commit();
    };

    issue(0, 0);
    issue(1, 1);

    const float4* zqp = g_zpf + g * 4 + t;

    // packed accumulators: [pillar][nt], lo word = even-d, hi word = odd-d
    ull zs[4][8];
#pragma unroll
    for (int p = 0; p < 4; p++)
#pragma unroll
        for (int nt = 0; nt < 8; nt++) zs[p][nt] = 0ULL;

#pragma unroll
    for (int c = 0; c < 4; c++) {
        if (c < 3) cp_wait<1>(); else cp_wait<0>();
        __syncwarp();

        // convert all 4 pillars' fragments
        uint32_t aH[4][4], aL[4][4];
#pragma unroll
        for (int p = 0; p < 4; p++) {
            const float4* sp = (const float4*)&s_x[warp][c & 1][p * 256];
            float4 f_lo = sp[g * 4 + t];
            float4 f_hi = sp[(g + 8) * 4 + t];
            cvt4(f_lo, aH[p][0], aH[p][2], aL[p][0], aL[p][2]);
            cvt4(f_hi, aH[p][1], aH[p][3], aL[p][1], aL[p][3]);
        }

#pragma unroll
        for (int j = 0; j < 4; j++) {
            float4 zq0 = zqp[j * (NZ * 4) + c * 64];
            float4 zq1 = zqp[j * (NZ * 4) + c * 64 + 32];
#pragma unroll
            for (int h = 0; h < 2; h++) {
                int nt = 2 * j + h;
                float c0 = h ? zq0.z : zq0.x, c1 = h ? zq0.w : zq0.y;
                float c2 = h ? zq1.z : zq1.x, c3 = h ? zq1.w : zq1.y;
#pragma unroll
                for (int p = 0; p < 4; p++) {
                    float d0, d1, d2, d3;
                    mma_c(d0, d1, d2, d3, aH[p][0], aH[p][1], aH[p][2], aH[p][3],
                          BH0[nt], BH1[nt], c0, c1, c2, c3);
                    mma_a(d0, d1, d2, d3, aH[p][0], aH[p][1], aH[p][2], aH[p][3],
                          BL0[nt], BL1[nt]);
                    mma_a(d0, d1, d2, d3, aL[p][0], aL[p][1], aL[p][2], aL[p][3],
                          BH0[nt], BH1[nt]);
                    relu_acc2(zs[p][nt], d0, d1, d2, d3);
                }
            }
        }

        __syncwarp();
        if (c + 2 < 4) issue(c & 1, c + 2);
    }

    // ---- per-pillar reduction + LN + store
#pragma unroll
    for (int p = 0; p < 4; p++) {
        float zsA[8], zsB[8];
#pragma unroll
        for (int nt = 0; nt < 8; nt++)
            unpk64(zs[p][nt], zsA[nt], zsB[nt]);
#pragma unroll
        for (int nt = 0; nt < 8; nt++) {
#pragma unroll
            for (int o = 4; o <= 16; o <<= 1) {
                zsA[nt] += __shfl_xor_sync(0xffffffffu, zsA[nt], o);
                zsB[nt] += __shfl_xor_sync(0xffffffffu, zsB[nt], o);
            }
        }
        float s = 0.f, sq = 0.f;
#pragma unroll
        for (int nt = 0; nt < 8; nt++) {
            s += zsA[nt] + zsB[nt];
            sq += zsA[nt] * zsA[nt] + zsB[nt] * zsB[nt];
        }
        s  += __shfl_xor_sync(0xffffffffu, s, 1);
        s  += __shfl_xor_sync(0xffffffffu, s, 2);
        sq += __shfl_xor_sync(0xffffffffu, sq, 1);
        sq += __shfl_xor_sync(0xffffffffu, sq, 2);

        float mean = s * (1.0f / 64.0f);
        float var  = sq * (1.0f / 64.0f) - mean * mean;
        float inv  = rsqrtf(var + LN_EPS);

        if (lane < 4) {
            float* op = out + ((size_t)quad * 4 + p) * ND;
#pragma unroll
            for (int nt = 0; nt < 8; nt++) {
                int d = nt * 8 + 2 * t;
                float2 ga = *(const float2*)&gamma_[d];
                float2 be = *(const float2*)&beta_[d];
                float2 o2;
                o2.x = (zsA[nt] - mean) * inv * ga.x + be.x;
                o2.y = (zsB[nt] - mean) * inv * ga.y + be.y;
                *(float2*)&op[d] = o2;
            }
        }
    }
}

// ---------------------------------------------------------------------------
// Launch
// ---------------------------------------------------------------------------
extern "C" void kernel_launch(void* const* d_in, const int* in_sizes, int n_in,
                              void* d_out, int out_size) {
    const float* vol     = (const float*)d_in[0];
    const float* z_embed = (const float*)d_in[1];
    const float* w1      = (const float*)d_in[2];
    const float* b1      = (const float*)d_in[3];
    const float* gamma_  = (const float*)d_in[4];
    const float* beta_   = (const float*)d_in[5];
    float* out = (float*)d_out;

    prep_kernel<<<32, 256>>>(z_embed, w1, b1);
    bev_hmma<<<NP / 16, 128>>>(vol, gamma_, beta_, out);
}

// round 14
// speedup vs baseline: 1.2633x; 1.2633x over previous
#include <cuda_runtime.h>
#include <cuda_fp16.h>
#include <cstdint>

#define NZ 64
#define NC 16
#define ND 64
#define NP 65536
#define NPAIR (NP / 2)
#define LN_EPS 1e-5f

typedef unsigned long long ull;

// Prepped constants (fp16 weight split: w = hi + lo exactly at prep time)
__device__ uint32_t g_wpk_hi[8 * ND];    // [kpair][d] fp16x2 hi
__device__ uint32_t g_wpk_lo[8 * ND];    // fp16x2 residual
// zpart in MMA-fragment order: [j][z][t] float4
__device__ float4 g_zpf[4 * NZ * 4];

__device__ __forceinline__ uint32_t pk_f16(float hi, float lo) {
    uint32_t r;
    asm("cvt.rn.f16x2.f32 %0, %1, %2;" : "=r"(r) : "f"(hi), "f"(lo));
    return r;
}

// D = A*B + C (fp16 inputs, fp32 accum)
__device__ __forceinline__ void mma_c(float& d0, float& d1, float& d2, float& d3,
                                      uint32_t a0, uint32_t a1, uint32_t a2, uint32_t a3,
                                      uint32_t b0, uint32_t b1,
                                      float c0, float c1, float c2, float c3) {
    asm("mma.sync.aligned.m16n8k16.row.col.f32.f16.f16.f32 "
        "{%0,%1,%2,%3},{%4,%5,%6,%7},{%8,%9},{%10,%11,%12,%13};"
        : "=f"(d0), "=f"(d1), "=f"(d2), "=f"(d3)
        : "r"(a0), "r"(a1), "r"(a2), "r"(a3), "r"(b0), "r"(b1),
          "f"(c0), "f"(c1), "f"(c2), "f"(c3));
}
// D += A*B
__device__ __forceinline__ void mma_a(float& d0, float& d1, float& d2, float& d3,
                                      uint32_t a0, uint32_t a1, uint32_t a2, uint32_t a3,
                                      uint32_t b0, uint32_t b1) {
    asm("mma.sync.aligned.m16n8k16.row.col.f32.f16.f16.f32 "
        "{%0,%1,%2,%3},{%4,%5,%6,%7},{%8,%9},{%0,%1,%2,%3};"
        : "+f"(d0), "+f"(d1), "+f"(d2), "+f"(d3)
        : "r"(a0), "r"(a1), "r"(a2), "r"(a3), "r"(b0), "r"(b1));
}

// relu 4 outputs, packed f32x2 accumulate
__device__ __forceinline__ void relu_acc2(ull& acc, float d0, float d1,
                                          float d2, float d3) {
    asm("{\n\t"
        ".reg .f32 r0, r1, r2, r3;\n\t"
        ".reg .b64 p, q;\n\t"
        "max.f32 r0, %1, 0f00000000;\n\t"
        "max.f32 r1, %2, 0f00000000;\n\t"
        "max.f32 r2, %3, 0f00000000;\n\t"
        "max.f32 r3, %4, 0f00000000;\n\t"
        "mov.b64 p, {r0, r1};\n\t"
        "mov.b64 q, {r2, r3};\n\t"
        "add.rn.f32x2 p, p, q;\n\t"
        "add.rn.f32x2 %0, %0, p;\n\t"
        "}"
        : "+l"(acc)
        : "f"(d0), "f"(d1), "f"(d2), "f"(d3));
}
__device__ __forceinline__ void unpk64(ull v, float& a, float& b) {
    asm("mov.b64 {%0, %1}, %2;" : "=f"(a), "=f"(b) : "l"(v));
}

// cp.async 16B global->shared
__device__ __forceinline__ void cp16(uint32_t smem_dst, const void* gsrc) {
    asm volatile("cp.async.cg.shared.global [%0], [%1], 16;\n"
                 :: "r"(smem_dst), "l"(gsrc) : "memory");
}
__device__ __forceinline__ void cp_commit() {
    asm volatile("cp.async.commit_group;\n" ::: "memory");
}
template <int N>
__device__ __forceinline__ void cp_wait() {
    asm volatile("cp.async.wait_group %0;\n" :: "n"(N) : "memory");
}

// ---------------------------------------------------------------------------
// Prologue — grid-wide; exact fp32 zpart; fp16 hi/lo weight split
// ---------------------------------------------------------------------------
__global__ void prep_kernel(const float* __restrict__ z_embed,
                            const float* __restrict__ w1,
                            const float* __restrict__ b1) {
    int tt = blockIdx.x * blockDim.x + threadIdx.x;
    int stride = gridDim.x * blockDim.x;
    for (int i = tt; i < NZ * ND; i += stride) {
        int z = i >> 6, d = i & 63;
        float s = b1[d];
#pragma unroll
        for (int c = 0; c < NC; c++)
            s += z_embed[z * NC + c] * w1[(NC + c) * ND + d];
        int j = d >> 4, r = d & 15;
        int t = (r & 7) >> 1;
        int slot = ((r >> 3) << 1) | (r & 1);
        ((float*)g_zpf)[(((j * NZ) + z) * 4 + t) * 4 + slot] = s;
    }
    for (int i = tt; i < 8 * ND; i += stride) {
        int kp = i >> 6, d = i & 63;
        float w0 = w1[(2 * kp) * ND + d];
        float w1v = w1[(2 * kp + 1) * ND + d];
        float h0 = __half2float(__float2half_rn(w0));
        float h1 = __half2float(__float2half_rn(w1v));
        g_wpk_hi[i] = pk_f16(h1, h0);
        g_wpk_lo[i] = pk_f16(w1v - h1, w0 - h0);
    }
}

// ---------------------------------------------------------------------------
// Main: 1 warp = 2 pillars; fp16 2-term split; cp.async double-buffered
// ---------------------------------------------------------------------------
__global__ __launch_bounds__(128, 4)
void bev_hmma(const float* __restrict__ vol,
              const float* __restrict__ gamma_,
              const float* __restrict__ beta_,
              float* __restrict__ out) {
    // per-warp double buffers: 512 floats = 2KB per (warp, buf)
    __shared__ __align__(16) float s_x[4][2][512];

    int tid = threadIdx.x;
    int warp = tid >> 5, lane = tid & 31;
    int g = lane >> 2, t = lane & 3;
    int pair = blockIdx.x * 4 + warp;

    // B fragments under K-permutation: b0 <-> kp 2t, b1 <-> kp 2t+1
    uint32_t BH0[8], BH1[8], BL0[8], BL1[8];
#pragma unroll
    for (int nt = 0; nt < 8; nt++) {
        int n = nt * 8 + g;
        BH0[nt] = g_wpk_hi[(2 * t) * ND + n];
        BH1[nt] = g_wpk_hi[(2 * t + 1) * ND + n];
        BL0[nt] = g_wpk_lo[(2 * t) * ND + n];
        BL1[nt] = g_wpk_lo[(2 * t + 1) * ND + n];
    }

    const float* gA = vol + (size_t)pair * 2048;   // pillar 2*pair
    const float* gB = gA + 1024;                   // pillar 2*pair+1

    uint32_t sb[2];
    sb[0] = (uint32_t)__cvta_generic_to_shared(&s_x[warp][0][0]);
    sb[1] = (uint32_t)__cvta_generic_to_shared(&s_x[warp][1][0]);

    // stage one chunk (2KB: A 1KB + B 1KB), 4 x cp16 per lane, coalesced
    auto issue = [&](int buf, int c) {
        uint32_t d0 = sb[buf] + lane * 16;
        const float* a = gA + c * 256 + lane * 4;
        const float* b = gB + c * 256 + lane * 4;
        cp16(d0, a);
        cp16(d0 + 512, a + 128);
        cp16(d0 + 1024, b);
        cp16(d0 + 1536, b + 128);
        cp_commit();
    };

    issue(0, 0);
    issue(1, 1);

    const float4* zqp = g_zpf + g * 4 + t;

    // packed accumulators: lo word = even-d col, hi word = odd-d col
    ull zs0[8], zs1[8];
#pragma unroll
    for (int nt = 0; nt < 8; nt++) { zs0[nt] = 0ULL; zs1[nt] = 0ULL; }

#pragma unroll
    for (int c = 0; c < 4; c++) {
        if (c < 3) cp_wait<1>(); else cp_wait<0>();
        __syncwarp();

        const float4* sp = (const float4*)&s_x[warp][c & 1][0];
        float4 fa_lo = sp[g * 4 + t];
        float4 fa_hi = sp[(g + 8) * 4 + t];
        float4 fb_lo = sp[64 + g * 4 + t];
        float4 fb_hi = sp[64 + (g + 8) * 4 + t];

        // A fragments: single fp16 rounding (no lo residual needed)
        uint32_t aA0 = pk_f16(fa_lo.y, fa_lo.x);
        uint32_t aA2 = pk_f16(fa_lo.w, fa_lo.z);
        uint32_t aA1 = pk_f16(fa_hi.y, fa_hi.x);
        uint32_t aA3 = pk_f16(fa_hi.w, fa_hi.z);
        uint32_t aB0 = pk_f16(fb_lo.y, fb_lo.x);
        uint32_t aB2 = pk_f16(fb_lo.w, fb_lo.z);
        uint32_t aB1 = pk_f16(fb_hi.y, fb_hi.x);
        uint32_t aB3 = pk_f16(fb_hi.w, fb_hi.z);

#pragma unroll
        for (int j = 0; j < 4; j++) {
            float4 zq0 = zqp[j * (NZ * 4) + c * 64];
            float4 zq1 = zqp[j * (NZ * 4) + c * 64 + 32];
#pragma unroll
            for (int h = 0; h < 2; h++) {
                int nt = 2 * j + h;
                float c0 = h ? zq0.z : zq0.x, c1 = h ? zq0.w : zq0.y;
                float c2 = h ? zq1.z : zq1.x, c3 = h ? zq1.w : zq1.y;

                float d0, d1, d2, d3;
                mma_c(d0, d1, d2, d3, aA0, aA1, aA2, aA3, BH0[nt], BH1[nt],
                      c0, c1, c2, c3);
                mma_a(d0, d1, d2, d3, aA0, aA1, aA2, aA3, BL0[nt], BL1[nt]);
                relu_acc2(zs0[nt], d0, d1, d2, d3);

                mma_c(d0, d1, d2, d3, aB0, aB1, aB2, aB3, BH0[nt], BH1[nt],
                      c0, c1, c2, c3);
                mma_a(d0, d1, d2, d3, aB0, aB1, aB2, aB3, BL0[nt], BL1[nt]);
                relu_acc2(zs1[nt], d0, d1, d2, d3);
            }
        }

        __syncwarp();
        if (c + 2 < 4) issue(c & 1, c + 2);
    }

    // ---- per-pillar reduction + LN + store
#pragma unroll
    for (int p = 0; p < 2; p++) {
        float zsA[8], zsB[8];
#pragma unroll
        for (int nt = 0; nt < 8; nt++)
            unpk64(p ? zs1[nt] : zs0[nt], zsA[nt], zsB[nt]);
#pragma unroll
        for (int nt = 0; nt < 8; nt++) {
#pragma unroll
            for (int o = 4; o <= 16; o <<= 1) {
                zsA[nt] += __shfl_xor_sync(0xffffffffu, zsA[nt], o);
                zsB[nt] += __shfl_xor_sync(0xffffffffu, zsB[nt], o);
            }
        }
        float s = 0.f, sq = 0.f;
#pragma unroll
        for (int nt = 0; nt < 8; nt++) {
            s += zsA[nt] + zsB[nt];
            sq += zsA[nt] * zsA[nt] + zsB[nt] * zsB[nt];
        }
        s  += __shfl_xor_sync(0xffffffffu, s, 1);
        s  += __shfl_xor_sync(0xffffffffu, s, 2);
        sq += __shfl_xor_sync(0xffffffffu, sq, 1);
        sq += __shfl_xor_sync(0xffffffffu, sq, 2);

        float mean = s * (1.0f / 64.0f);
        float var  = sq * (1.0f / 64.0f) - mean * mean;
        float inv  = rsqrtf(var + LN_EPS);

        if (lane < 4) {
            float* op = out + ((size_t)pair * 2 + p) * ND;
#pragma unroll
            for (int nt = 0; nt < 8; nt++) {
                int d = nt * 8 + 2 * t;
                float2 ga = *(const float2*)&gamma_[d];
                float2 be = *(const float2*)&beta_[d];
                float2 o2;
                o2.x = (zsA[nt] - mean) * inv * ga.x + be.x;
                o2.y = (zsB[nt] - mean) * inv * ga.y + be.y;
                *(float2*)&op[d] = o2;
            }
        }
    }
}

// ---------------------------------------------------------------------------
// Launch
// ---------------------------------------------------------------------------
extern "C" void kernel_launch(void* const* d_in, const int* in_sizes, int n_in,
                              void* d_out, int out_size) {
    const float* vol     = (const float*)d_in[0];
    const float* z_embed = (const float*)d_in[1];
    const float* w1      = (const float*)d_in[2];
    const float* b1      = (const float*)d_in[3];
    const float* gamma_  = (const float*)d_in[4];
    const float* beta_   = (const float*)d_in[5];
    float* out = (float*)d_out;

    prep_kernel<<<32, 256>>>(z_embed, w1, b1);
    bev_hmma<<<NPAIR / 4, 128>>>(vol, gamma_, beta_, out);
}